// round 7
// baseline (speedup 1.0000x reference)
#include <cuda_runtime.h>
#include <cstdint>

// Problem constants (fixed by setup_inputs)
#define B_   8
#define QL   1024
#define SL   2048
#define DM   1024
#define H_   16
#define DH   64
#define QT   128          // q rows per CTA
#define STT  128          // s cols per chunk
#define NCH  (SL/STT)     // 16

// smem strides (floats) chosen for conflict-free mma fragment loads
#define QS_S 68   // stride%32==4 -> A-frag banks 4g+lt distinct
#define KS_S 68
#define VS_S 72   // stride%32==8 -> B-frag (PV) banks 8*lt+g distinct
#define PS_S 132  // float4-aligned, conflict-free A-frag (PV)

// floats: Q 128*68 + K 128*68 + V 2*128*72 + P 128*132 + mask 2048 + Rs 256 + Is 128
#define SMEM_FLOATS (QT*QS_S + STT*KS_S + 2*STT*VS_S + QT*PS_S + SL + 256 + 128)

__device__ __forceinline__ float tf32r(float x) {
    uint32_t u;
    asm("cvt.rna.tf32.f32 %0, %1;" : "=r"(u) : "f"(x));
    return __uint_as_float(u);
}

__device__ __forceinline__ void mma8(float d[4], const uint32_t a[4], const uint32_t b[2]) {
    asm("mma.sync.aligned.m16n8k8.row.col.f32.tf32.tf32.f32 "
        "{%0,%1,%2,%3},{%4,%5,%6,%7},{%8,%9},{%0,%1,%2,%3};\n"
        : "+f"(d[0]), "+f"(d[1]), "+f"(d[2]), "+f"(d[3])
        : "r"(a[0]), "r"(a[1]), "r"(a[2]), "r"(a[3]), "r"(b[0]), "r"(b[1]));
}

__device__ __forceinline__ void cp_async16(uint32_t smem_addr, const void* gptr) {
    asm volatile("cp.async.cg.shared.global [%0], [%1], 16;\n"
                 :: "r"(smem_addr), "l"(gptr));
}
__device__ __forceinline__ void cp_commit() {
    asm volatile("cp.async.commit_group;\n");
}
__device__ __forceinline__ void cp_wait0() {
    asm volatile("cp.async.wait_group 0;\n");
}

// QK^T for one 128x128 chunk. Warp grid 4(q) x 2(s): warp tile 32(q) x 64(s).
__device__ __forceinline__ void qk_chunk(const float* __restrict__ Qs,
                                         const float* __restrict__ Ks,
                                         float acc[2][8][4],
                                         int wm, int wn, int g, int lt) {
    #pragma unroll
    for (int kk = 0; kk < 8; kk++) {
        uint32_t afr[2][4];
        #pragma unroll
        for (int mi = 0; mi < 2; mi++) {
            int r = wm * 32 + mi * 16 + g;
            afr[mi][0] = __float_as_uint(Qs[r * QS_S + kk * 8 + lt]);
            afr[mi][1] = __float_as_uint(Qs[(r + 8) * QS_S + kk * 8 + lt]);
            afr[mi][2] = __float_as_uint(Qs[r * QS_S + kk * 8 + lt + 4]);
            afr[mi][3] = __float_as_uint(Qs[(r + 8) * QS_S + kk * 8 + lt + 4]);
        }
        #pragma unroll
        for (int ni = 0; ni < 8; ni++) {
            int c = wn * 64 + ni * 8 + g;
            uint32_t bfr[2];
            bfr[0] = __float_as_uint(Ks[c * KS_S + kk * 8 + lt]);
            bfr[1] = __float_as_uint(Ks[c * KS_S + kk * 8 + lt + 4]);
            mma8(acc[0][ni], afr[0], bfr);
            mma8(acc[1][ni], afr[1], bfr);
        }
    }
}

extern "C" __global__ void __launch_bounds__(256, 1)
mha_fused_kernel(const float* __restrict__ Qg, const float* __restrict__ Kg,
                 const float* __restrict__ Vg, const int* __restrict__ Mg,
                 float* __restrict__ Og, float* __restrict__ Ag, int write_attn) {
    extern __shared__ float smf[];
    float* Qs = smf;
    float* Ks = Qs + QT * QS_S;
    float* Vs = Ks + STT * KS_S;      // two buffers of STT*VS_S
    float* Ps = Vs + 2 * STT * VS_S;
    float* Ms = Ps + QT * PS_S;       // mask row, SL floats
    float* Rs = Ms + SL;              // 2 x 128 partial rowsums (per wn)
    float* Is = Rs + 256;             // 1/rowsum

    const int tid = threadIdx.x;
    const int lane = tid & 31, wid = tid >> 5;
    const int g = lane >> 2, lt = lane & 3;
    const int wm = wid >> 1, wn = wid & 1;
    const int b = blockIdx.z, h = blockIdx.y, q0 = blockIdx.x * QT;

    const float* gkb = Kg + ((size_t)b * SL) * DM + h * DH;
    const float* gvb = Vg + ((size_t)b * SL) * DM + h * DH;

    // per-thread staging coords (8 float4 per chunk)
    int srow[8], scol[8];
    #pragma unroll
    for (int j = 0; j < 8; j++) {
        int idx = tid + j * 256;
        srow[j] = idx >> 4;
        scol[j] = (idx & 15) << 2;
    }

    // ---- init: mask row, rowsum partials, Q tile (scaled 1/8, tf32 RNA) ----
    for (int j = tid; j < SL; j += 256) Ms[j] = (float)Mg[b * SL + j];
    if (tid < 256) Rs[tid] = 0.f;
    {
        const float* gq = Qg + ((size_t)(b * QL + q0)) * DM + h * DH;
        #pragma unroll
        for (int j = 0; j < 8; j++) {
            float4 v = *(const float4*)(gq + (size_t)srow[j] * DM + scol[j]);
            float4 w;
            w.x = tf32r(v.x * 0.125f); w.y = tf32r(v.y * 0.125f);
            w.z = tf32r(v.z * 0.125f); w.w = tf32r(v.w * 0.125f);
            *(float4*)(Qs + srow[j] * QS_S + scol[j]) = w;
        }
    }

    // ================= Phase 1: rowsums of exp(z)*mask =================
    float4 kreg[8];
    #pragma unroll
    for (int j = 0; j < 8; j++)
        kreg[j] = *(const float4*)(gkb + (size_t)srow[j] * DM + scol[j]);

    for (int sc = 0; sc < NCH; sc++) {
        __syncthreads();   // Ks free (prev compute done; first iter: init done)
        #pragma unroll
        for (int j = 0; j < 8; j++) {
            float4 w;
            w.x = tf32r(kreg[j].x); w.y = tf32r(kreg[j].y);
            w.z = tf32r(kreg[j].z); w.w = tf32r(kreg[j].w);
            *(float4*)(Ks + srow[j] * KS_S + scol[j]) = w;
        }
        __syncthreads();
        if (sc + 1 < NCH) {
            const float* gk = gkb + (size_t)(sc + 1) * STT * DM;
            #pragma unroll
            for (int j = 0; j < 8; j++)
                kreg[j] = *(const float4*)(gk + (size_t)srow[j] * DM + scol[j]);
        }

        float acc[2][8][4];
        #pragma unroll
        for (int mi = 0; mi < 2; mi++)
            #pragma unroll
            for (int ni = 0; ni < 8; ni++)
                #pragma unroll
                for (int j = 0; j < 4; j++) acc[mi][ni][j] = 0.f;

        qk_chunk(Qs, Ks, acc, wm, wn, g, lt);

        const int s0 = sc * STT;
        #pragma unroll
        for (int mi = 0; mi < 2; mi++)
            #pragma unroll
            for (int half = 0; half < 2; half++) {
                int r = wm * 32 + mi * 16 + g + half * 8;
                float rs = 0.f;
                #pragma unroll
                for (int ni = 0; ni < 8; ni++) {
                    int c = wn * 64 + ni * 8 + 2 * lt;
                    rs += __expf(acc[mi][ni][half * 2 + 0]) * Ms[s0 + c];
                    rs += __expf(acc[mi][ni][half * 2 + 1]) * Ms[s0 + c + 1];
                }
                rs += __shfl_xor_sync(0xffffffffu, rs, 1);
                rs += __shfl_xor_sync(0xffffffffu, rs, 2);
                if (lt == 0) Rs[wn * 128 + r] += rs;  // unique (warp,row) slot
            }
    }

    __syncthreads();
    if (tid < QT) Is[tid] = 1.0f / (Rs[tid] + Rs[128 + tid] + 1e-13f);

    // ================= Phase 2: recompute, write normalized attn, PV =================
    float oacc[8][4];  // warp tile 16(q) x 64(dv): warp w owns rows 16w..16w+15
    #pragma unroll
    for (int ni = 0; ni < 8; ni++)
        #pragma unroll
        for (int j = 0; j < 4; j++) oacc[ni][j] = 0.f;

    // prologue: K0 -> regs, V0 -> cp.async buffer 0
    #pragma unroll
    for (int j = 0; j < 8; j++)
        kreg[j] = *(const float4*)(gkb + (size_t)srow[j] * DM + scol[j]);
    {
        const uint32_t vdst = (uint32_t)__cvta_generic_to_shared(Vs);
        #pragma unroll
        for (int j = 0; j < 8; j++)
            cp_async16(vdst + (uint32_t)(srow[j] * VS_S + scol[j]) * 4,
                       gvb + (size_t)srow[j] * DM + scol[j]);
        cp_commit();
    }

    for (int sc = 0; sc < NCH; sc++) {
        const int s0 = sc * STT;
        float* Vcur = Vs + (sc & 1) * STT * VS_S;
        __syncthreads();   // prev compute done: Ks free, V[(sc)&1] not being read
        #pragma unroll
        for (int j = 0; j < 8; j++) {
            float4 w;
            w.x = tf32r(kreg[j].x); w.y = tf32r(kreg[j].y);
            w.z = tf32r(kreg[j].z); w.w = tf32r(kreg[j].w);
            *(float4*)(Ks + srow[j] * KS_S + scol[j]) = w;
        }
        cp_wait0();        // V(sc) arrived in Vcur
        __syncthreads();   // Ks + Vcur visible to all
        if (sc + 1 < NCH) {
            const float* gk = gkb + (size_t)(sc + 1) * STT * DM;
            #pragma unroll
            for (int j = 0; j < 8; j++)
                kreg[j] = *(const float4*)(gk + (size_t)srow[j] * DM + scol[j]);
            const float* gv = gvb + (size_t)(sc + 1) * STT * DM;
            const uint32_t vdst = (uint32_t)__cvta_generic_to_shared(
                Vs + ((sc + 1) & 1) * STT * VS_S);
            #pragma unroll
            for (int j = 0; j < 8; j++)
                cp_async16(vdst + (uint32_t)(srow[j] * VS_S + scol[j]) * 4,
                           gv + (size_t)srow[j] * DM + scol[j]);
            cp_commit();
        }

        float acc[2][8][4];
        #pragma unroll
        for (int mi = 0; mi < 2; mi++)
            #pragma unroll
            for (int ni = 0; ni < 8; ni++)
                #pragma unroll
                for (int j = 0; j < 4; j++) acc[mi][ni][j] = 0.f;

        qk_chunk(Qs, Ks, acc, wm, wn, g, lt);

        // normalized p -> Ps, stored tf32-rounded (serves attn store AND PV A-frags)
        #pragma unroll
        for (int mi = 0; mi < 2; mi++)
            #pragma unroll
            for (int half = 0; half < 2; half++) {
                int r = wm * 32 + mi * 16 + g + half * 8;
                float iv = Is[r];
                #pragma unroll
                for (int ni = 0; ni < 8; ni++) {
                    int c = wn * 64 + ni * 8 + 2 * lt;
                    float2 pv;
                    pv.x = tf32r(__expf(acc[mi][ni][half * 2 + 0]) * Ms[s0 + c] * iv);
                    pv.y = tf32r(__expf(acc[mi][ni][half * 2 + 1]) * Ms[s0 + c + 1] * iv);
                    *(float2*)(Ps + r * PS_S + c) = pv;
                }
            }
        __syncthreads();

        // coalesced streaming write of the normalized attention tile
        if (write_attn) {
            for (int i = tid; i < QT * STT / 4; i += 256) {
                int r = i >> 5, c4 = (i & 31) << 2;
                float4 v = *(const float4*)(Ps + r * PS_S + c4);
                __stcs((float4*)(Ag + (size_t)((b * QL + q0 + r) * H_ + h) * SL + s0 + c4), v);
            }
        }

        // PV: O[128x64] += P[128x128] @ V[128x64]
        #pragma unroll
        for (int kk = 0; kk < 16; kk++) {
            uint32_t afr[4];
            int r = wid * 16 + g;
            afr[0] = __float_as_uint(Ps[r * PS_S + kk * 8 + lt]);
            afr[1] = __float_as_uint(Ps[(r + 8) * PS_S + kk * 8 + lt]);
            afr[2] = __float_as_uint(Ps[r * PS_S + kk * 8 + lt + 4]);
            afr[3] = __float_as_uint(Ps[(r + 8) * PS_S + kk * 8 + lt + 4]);
            #pragma unroll
            for (int ni = 0; ni < 8; ni++) {
                uint32_t bfr[2];
                bfr[0] = __float_as_uint(Vcur[(kk * 8 + lt) * VS_S + ni * 8 + g]);
                bfr[1] = __float_as_uint(Vcur[(kk * 8 + lt + 4) * VS_S + ni * 8 + g]);
                mma8(oacc[ni], afr, bfr);
            }
        }
    }

    // ---- write O tile ----
    {
        int r = wid * 16 + g;
        float* go = Og + ((size_t)(b * QL + q0 + r)) * DM + h * DH;
        #pragma unroll
        for (int ni = 0; ni < 8; ni++) {
            int c = ni * 8 + 2 * lt;
            float2 v0; v0.x = oacc[ni][0]; v0.y = oacc[ni][1];
            float2 v1; v1.x = oacc[ni][2]; v1.y = oacc[ni][3];
            __stcs((float2*)(go + c), v0);
            __stcs((float2*)(go + (size_t)8 * DM + c), v1);
        }
    }
}

extern "C" void kernel_launch(void* const* d_in, const int* in_sizes, int n_in,
                              void* d_out, int out_size) {
    const float* Qg = (const float*)d_in[0];
    const float* Kg = (const float*)d_in[1];
    const float* Vg = (const float*)d_in[2];
    const int*   Mg = (const int*)d_in[3];

    float* Og = (float*)d_out;
    float* Ag = Og + (size_t)B_ * QL * DM;  // attention follows `out` in d_out

    const long long need = (long long)B_ * QL * DM + (long long)B_ * QL * H_ * SL;
    int write_attn = ((long long)out_size >= need) ? 1 : 0;

    cudaFuncSetAttribute(mha_fused_kernel,
                         cudaFuncAttributeMaxDynamicSharedMemorySize,
                         SMEM_FLOATS * (int)sizeof(float));

    dim3 grid(QL / QT, H_, B_);
    mha_fused_kernel<<<grid, 256, SMEM_FLOATS * sizeof(float)>>>(
        Qg, Kg, Vg, Mg, Og, Ag, write_attn);
}

// round 8
// speedup vs baseline: 1.4279x; 1.4279x over previous
#include <cuda_runtime.h>
#include <cstdint>

// Problem constants (fixed by setup_inputs)
#define B_   8
#define QL   1024
#define SL   2048
#define DM   1024
#define H_   16
#define DH   64
#define QT   128          // q rows per CTA
#define STT  128          // s cols per chunk (K1)
#define NCH  (SL/STT)     // 16

#define KS_S 68           // K tile stride: banks 4g+lt distinct for B-frags
#define PS_S 132          // P staging stride, float4-aligned, conflict-free

// K1 smem floats: Ks 128*68 + Ps 128*132 + mask 2048 + Rs 256 + Is 128
#define K1_SMEM_FLOATS (STT*KS_S + QT*PS_S + SL + 256 + 128)

// K2 (PV GEMM) config
#define KC   64           // k-chunk (s dimension)
#define NKC  (SL/KC)      // 32
#define AS_S 68           // attn tile stride (A-frag conflict-free)
#define VS_S 72           // V tile stride (B-frag conflict-free)
#define K2_SMEM_FLOATS (2*QT*AS_S + 2*KC*VS_S)   // double-buffered

__device__ __forceinline__ float tf32r(float x) {
    uint32_t u;
    asm("cvt.rna.tf32.f32 %0, %1;" : "=r"(u) : "f"(x));
    return __uint_as_float(u);
}
__device__ __forceinline__ uint32_t tf32b(float x) {
    uint32_t u;
    asm("cvt.rna.tf32.f32 %0, %1;" : "=r"(u) : "f"(x));
    return u;
}

__device__ __forceinline__ void mma8(float d[4], const uint32_t a[4], const uint32_t b[2]) {
    asm("mma.sync.aligned.m16n8k8.row.col.f32.tf32.tf32.f32 "
        "{%0,%1,%2,%3},{%4,%5,%6,%7},{%8,%9},{%0,%1,%2,%3};\n"
        : "+f"(d[0]), "+f"(d[1]), "+f"(d[2]), "+f"(d[3])
        : "r"(a[0]), "r"(a[1]), "r"(a[2]), "r"(a[3]), "r"(b[0]), "r"(b[1]));
}

__device__ __forceinline__ void cp_async16(uint32_t smem_addr, const void* gptr) {
    asm volatile("cp.async.cg.shared.global [%0], [%1], 16;\n"
                 :: "r"(smem_addr), "l"(gptr));
}
__device__ __forceinline__ void cp_commit() {
    asm volatile("cp.async.commit_group;\n");
}
__device__ __forceinline__ void cp_wait1() {
    asm volatile("cp.async.wait_group 1;\n");
}

// ===================== K1: scores + softmax-normalize + attn write =====================
// Q-fragments live in registers for the whole kernel (no A-frag LDS in QK).
extern "C" __global__ void __launch_bounds__(256, 1)
mha_qk_kernel(const float* __restrict__ Qg, const float* __restrict__ Kg,
              const int* __restrict__ Mg, float* __restrict__ Ag) {
    extern __shared__ float smf[];
    float* Ks = smf;
    float* Ps = Ks + STT * KS_S;
    float* Ms = Ps + QT * PS_S;   // mask row, SL floats
    float* Rs = Ms + SL;          // 2 x 128 partial rowsums (per wn)
    float* Is = Rs + 256;         // 1/rowsum

    const int tid = threadIdx.x;
    const int lane = tid & 31, wid = tid >> 5;
    const int g = lane >> 2, lt = lane & 3;
    const int wm = wid >> 1, wn = wid & 1;
    const int b = blockIdx.z, h = blockIdx.y, q0 = blockIdx.x * QT;

    const float* gkb = Kg + ((size_t)b * SL) * DM + h * DH;

    // ---- init: mask row, rowsum partials ----
    for (int j = tid; j < SL; j += 256) Ms[j] = (float)Mg[b * SL + j];
    if (tid < 256) Rs[tid] = 0.f;

    // ---- Q fragments straight from gmem into registers (scale 1/8, tf32 RNA) ----
    uint32_t qfr[2][8][4];
    {
        const float* gq = Qg + ((size_t)(b * QL + q0)) * DM + h * DH;
        #pragma unroll
        for (int mi = 0; mi < 2; mi++) {
            int r = wm * 32 + mi * 16 + g;
            #pragma unroll
            for (int kk = 0; kk < 8; kk++) {
                qfr[mi][kk][0] = tf32b(__ldg(gq + (size_t)r * DM + kk * 8 + lt) * 0.125f);
                qfr[mi][kk][1] = tf32b(__ldg(gq + (size_t)(r + 8) * DM + kk * 8 + lt) * 0.125f);
                qfr[mi][kk][2] = tf32b(__ldg(gq + (size_t)r * DM + kk * 8 + lt + 4) * 0.125f);
                qfr[mi][kk][3] = tf32b(__ldg(gq + (size_t)(r + 8) * DM + kk * 8 + lt + 4) * 0.125f);
            }
        }
    }

    // ================= Phase 1: rowsums of exp(z)*mask =================
    for (int sc = 0; sc < NCH; sc++) {
        const int s0 = sc * STT;
        __syncthreads();   // Ks free
        const float* gk = gkb + (size_t)s0 * DM;
        for (int i = tid; i < STT * DH / 4; i += 256) {
            int r = i >> 4, c4 = (i & 15) << 2;
            float4 v = *(const float4*)(gk + (size_t)r * DM + c4);
            float4 w;
            w.x = tf32r(v.x); w.y = tf32r(v.y); w.z = tf32r(v.z); w.w = tf32r(v.w);
            *(float4*)(Ks + r * KS_S + c4) = w;
        }
        __syncthreads();

        float acc[2][8][4];
        #pragma unroll
        for (int mi = 0; mi < 2; mi++)
            #pragma unroll
            for (int ni = 0; ni < 8; ni++)
                #pragma unroll
                for (int j = 0; j < 4; j++) acc[mi][ni][j] = 0.f;

        #pragma unroll
        for (int kk = 0; kk < 8; kk++) {
            #pragma unroll
            for (int ni = 0; ni < 8; ni++) {
                int c = wn * 64 + ni * 8 + g;
                uint32_t bfr[2];
                bfr[0] = __float_as_uint(Ks[c * KS_S + kk * 8 + lt]);
                bfr[1] = __float_as_uint(Ks[c * KS_S + kk * 8 + lt + 4]);
                mma8(acc[0][ni], qfr[0][kk], bfr);
                mma8(acc[1][ni], qfr[1][kk], bfr);
            }
        }

        #pragma unroll
        for (int mi = 0; mi < 2; mi++)
            #pragma unroll
            for (int half = 0; half < 2; half++) {
                int r = wm * 32 + mi * 16 + g + half * 8;
                float rs = 0.f;
                #pragma unroll
                for (int ni = 0; ni < 8; ni++) {
                    int c = wn * 64 + ni * 8 + 2 * lt;
                    rs += __expf(acc[mi][ni][half * 2 + 0]) * Ms[s0 + c];
                    rs += __expf(acc[mi][ni][half * 2 + 1]) * Ms[s0 + c + 1];
                }
                rs += __shfl_xor_sync(0xffffffffu, rs, 1);
                rs += __shfl_xor_sync(0xffffffffu, rs, 2);
                if (lt == 0) Rs[wn * 128 + r] += rs;  // unique (warp,row) slot
            }
    }

    __syncthreads();
    if (tid < QT) Is[tid] = 1.0f / (Rs[tid] + Rs[128 + tid] + 1e-13f);

    // ================= Phase 2: recompute, write normalized attn =================
    for (int sc = 0; sc < NCH; sc++) {
        const int s0 = sc * STT;
        __syncthreads();   // Ks free, Ps readers done
        const float* gk = gkb + (size_t)s0 * DM;
        for (int i = tid; i < STT * DH / 4; i += 256) {
            int r = i >> 4, c4 = (i & 15) << 2;
            float4 v = *(const float4*)(gk + (size_t)r * DM + c4);
            float4 w;
            w.x = tf32r(v.x); w.y = tf32r(v.y); w.z = tf32r(v.z); w.w = tf32r(v.w);
            *(float4*)(Ks + r * KS_S + c4) = w;
        }
        __syncthreads();

        float acc[2][8][4];
        #pragma unroll
        for (int mi = 0; mi < 2; mi++)
            #pragma unroll
            for (int ni = 0; ni < 8; ni++)
                #pragma unroll
                for (int j = 0; j < 4; j++) acc[mi][ni][j] = 0.f;

        #pragma unroll
        for (int kk = 0; kk < 8; kk++) {
            #pragma unroll
            for (int ni = 0; ni < 8; ni++) {
                int c = wn * 64 + ni * 8 + g;
                uint32_t bfr[2];
                bfr[0] = __float_as_uint(Ks[c * KS_S + kk * 8 + lt]);
                bfr[1] = __float_as_uint(Ks[c * KS_S + kk * 8 + lt + 4]);
                mma8(acc[0][ni], qfr[0][kk], bfr);
                mma8(acc[1][ni], qfr[1][kk], bfr);
            }
        }

        // normalized p -> Ps (full fp32: attention output is exact softmax here)
        #pragma unroll
        for (int mi = 0; mi < 2; mi++)
            #pragma unroll
            for (int half = 0; half < 2; half++) {
                int r = wm * 32 + mi * 16 + g + half * 8;
                float iv = Is[r];
                #pragma unroll
                for (int ni = 0; ni < 8; ni++) {
                    int c = wn * 64 + ni * 8 + 2 * lt;
                    float2 pv;
                    pv.x = __expf(acc[mi][ni][half * 2 + 0]) * Ms[s0 + c] * iv;
                    pv.y = __expf(acc[mi][ni][half * 2 + 1]) * Ms[s0 + c + 1] * iv;
                    *(float2*)(Ps + r * PS_S + c) = pv;
                }
            }
        __syncthreads();

        // coalesced streaming write of the normalized attention tile
        for (int i = tid; i < QT * STT / 4; i += 256) {
            int r = i >> 5, c4 = (i & 31) << 2;
            float4 v = *(const float4*)(Ps + r * PS_S + c4);
            __stcs((float4*)(Ag + (size_t)((b * QL + q0 + r) * H_ + h) * SL + s0 + c4), v);
        }
    }
}

// ===================== K2: O = attn @ V (tf32 GEMM, occ 2, cp.async dbuf) =====================
extern "C" __global__ void __launch_bounds__(256, 2)
mha_pv_kernel(const float* __restrict__ Ag, const float* __restrict__ Vg,
              float* __restrict__ Og) {
    extern __shared__ float smf[];
    float* As = smf;                       // 2 x 128 x AS_S
    float* Vs = As + 2 * QT * AS_S;        // 2 x 64 x VS_S

    const int tid = threadIdx.x;
    const int lane = tid & 31, wid = tid >> 5;
    const int g = lane >> 2, lt = lane & 3;
    const int wm = wid >> 1, wn = wid & 1;   // 4(q) x 2(dv) warp grid, tile 32x32
    const int b = blockIdx.z, h = blockIdx.y, q0 = blockIdx.x * QT;

    const uint32_t as_base = (uint32_t)__cvta_generic_to_shared(As);
    const uint32_t vs_base = (uint32_t)__cvta_generic_to_shared(Vs);

    // staging coords
    int ar[8], ac[8];
    #pragma unroll
    for (int j = 0; j < 8; j++) {
        int idx = tid + j * 256;           // 0..2047 -> 128 x 64 floats /4
        ar[j] = idx >> 4;
        ac[j] = (idx & 15) << 2;
    }
    int vr[4], vc[4];
    #pragma unroll
    for (int j = 0; j < 4; j++) {
        int idx = tid + j * 256;           // 0..1023 -> 64 x 64 floats /4
        vr[j] = idx >> 4;
        vc[j] = (idx & 15) << 2;
    }

    const float* gab = Ag + ((size_t)((b * QL + q0) * H_ + h)) * SL;  // row stride H_*SL
    const float* gvb = Vg + ((size_t)b * SL) * DM + h * DH;

    // stage chunk kc into buffer bi
    auto stage = [&](int kc, int bi) {
        const int s0 = kc * KC;
        const uint32_t ad = as_base + (uint32_t)(bi * QT * AS_S) * 4;
        #pragma unroll
        for (int j = 0; j < 8; j++)
            cp_async16(ad + (uint32_t)(ar[j] * AS_S + ac[j]) * 4,
                       gab + (size_t)ar[j] * (H_ * SL) + s0 + ac[j]);
        const uint32_t vd = vs_base + (uint32_t)(bi * KC * VS_S) * 4;
        #pragma unroll
        for (int j = 0; j < 4; j++)
            cp_async16(vd + (uint32_t)(vr[j] * VS_S + vc[j]) * 4,
                       gvb + (size_t)(s0 + vr[j]) * DM + vc[j]);
        cp_commit();
    };

    float oacc[2][4][4];
    #pragma unroll
    for (int mi = 0; mi < 2; mi++)
        #pragma unroll
        for (int ni = 0; ni < 4; ni++)
            #pragma unroll
            for (int j = 0; j < 4; j++) oacc[mi][ni][j] = 0.f;

    stage(0, 0);

    for (int kc = 0; kc < NKC; kc++) {
        if (kc + 1 < NKC) stage(kc + 1, (kc + 1) & 1);
        else cp_commit();                  // keep wait_group count consistent
        cp_wait1();                        // chunk kc resident
        __syncthreads();

        const float* Ac = As + (kc & 1) * QT * AS_S;
        const float* Vc = Vs + (kc & 1) * KC * VS_S;

        #pragma unroll
        for (int kk = 0; kk < 8; kk++) {
            uint32_t afr[2][4];
            #pragma unroll
            for (int mi = 0; mi < 2; mi++) {
                int r = wm * 32 + mi * 16 + g;
                afr[mi][0] = __float_as_uint(Ac[r * AS_S + kk * 8 + lt]);
                afr[mi][1] = __float_as_uint(Ac[(r + 8) * AS_S + kk * 8 + lt]);
                afr[mi][2] = __float_as_uint(Ac[r * AS_S + kk * 8 + lt + 4]);
                afr[mi][3] = __float_as_uint(Ac[(r + 8) * AS_S + kk * 8 + lt + 4]);
            }
            #pragma unroll
            for (int ni = 0; ni < 4; ni++) {
                int c = wn * 32 + ni * 8 + g;
                uint32_t bfr[2];
                bfr[0] = __float_as_uint(Vc[(kk * 8 + lt) * VS_S + c]);
                bfr[1] = __float_as_uint(Vc[(kk * 8 + lt + 4) * VS_S + c]);
                mma8(oacc[0][ni], afr[0], bfr);
                mma8(oacc[1][ni], afr[1], bfr);
            }
        }
        __syncthreads();   // readers done before this buffer is restaged
    }

    // ---- write O tile (warp tile 32q x 32dv) ----
    #pragma unroll
    for (int mi = 0; mi < 2; mi++) {
        int r = wm * 32 + mi * 16 + g;
        float* go = Og + ((size_t)(b * QL + q0 + r)) * DM + h * DH + wn * 32;
        #pragma unroll
        for (int ni = 0; ni < 4; ni++) {
            int c = ni * 8 + 2 * lt;
            float2 v0; v0.x = oacc[mi][ni][0]; v0.y = oacc[mi][ni][1];
            float2 v1; v1.x = oacc[mi][ni][2]; v1.y = oacc[mi][ni][3];
            __stcs((float2*)(go + c), v0);
            __stcs((float2*)(go + (size_t)8 * DM + c), v1);
        }
    }
}

extern "C" void kernel_launch(void* const* d_in, const int* in_sizes, int n_in,
                              void* d_out, int out_size) {
    const float* Qg = (const float*)d_in[0];
    const float* Kg = (const float*)d_in[1];
    const float* Vg = (const float*)d_in[2];
    const int*   Mg = (const int*)d_in[3];

    float* Og = (float*)d_out;
    float* Ag = Og + (size_t)B_ * QL * DM;   // attention region of d_out

    cudaFuncSetAttribute(mha_qk_kernel,
                         cudaFuncAttributeMaxDynamicSharedMemorySize,
                         K1_SMEM_FLOATS * (int)sizeof(float));
    cudaFuncSetAttribute(mha_pv_kernel,
                         cudaFuncAttributeMaxDynamicSharedMemorySize,
                         K2_SMEM_FLOATS * (int)sizeof(float));

    dim3 grid(QL / QT, H_, B_);
    mha_qk_kernel<<<grid, 256, K1_SMEM_FLOATS * sizeof(float)>>>(Qg, Kg, Mg, Ag);
    mha_pv_kernel<<<grid, 256, K2_SMEM_FLOATS * sizeof(float)>>>(Ag, Vg, Og);
}

// round 9
// speedup vs baseline: 2.0339x; 1.4244x over previous
#include <cuda_runtime.h>
#include <cstdint>

// Problem constants (fixed by setup_inputs)
#define B_   8
#define QL   1024
#define SL   2048
#define DM   1024
#define H_   16
#define DH   64
#define QT   128          // q rows per CTA
#define STT  128          // s cols per chunk (K1)
#define NCH  (SL/STT)     // 16

#define KS_S 68           // K tile stride: banks 4g+lt distinct for B-frags
// K1 smem floats: 2 x (128*68) K dbuf + mask 2048 + Rs 512
#define K1_SMEM_FLOATS (2*STT*KS_S + SL + 512)

// K2 (normalize + PV GEMM) config
#define KC   64           // k-chunk (s dimension)
#define NKC  (SL/KC)      // 32
#define AS_S 68           // e tile stride (A-frag conflict-free)
#define VS_S 72           // V tile stride (B-frag conflict-free)
#define K2_SMEM_FLOATS (2*QT*AS_S + 2*KC*VS_S + 128)

// per-(b,h,q) 1/rowsum scratch
__device__ float InvG[(size_t)B_ * H_ * QL];

__device__ __forceinline__ uint32_t tf32b(float x) {
    uint32_t u;
    asm("cvt.rna.tf32.f32 %0, %1;" : "=r"(u) : "f"(x));
    return u;
}

__device__ __forceinline__ void mma8(float d[4], const uint32_t a[4], const uint32_t b[2]) {
    asm("mma.sync.aligned.m16n8k8.row.col.f32.tf32.tf32.f32 "
        "{%0,%1,%2,%3},{%4,%5,%6,%7},{%8,%9},{%0,%1,%2,%3};\n"
        : "+f"(d[0]), "+f"(d[1]), "+f"(d[2]), "+f"(d[3])
        : "r"(a[0]), "r"(a[1]), "r"(a[2]), "r"(a[3]), "r"(b[0]), "r"(b[1]));
}

__device__ __forceinline__ void cp_async16(uint32_t smem_addr, const void* gptr) {
    asm volatile("cp.async.cg.shared.global [%0], [%1], 16;\n"
                 :: "r"(smem_addr), "l"(gptr));
}
__device__ __forceinline__ void cp_commit() {
    asm volatile("cp.async.commit_group;\n");
}
__device__ __forceinline__ void cp_wait1() {
    asm volatile("cp.async.wait_group 1;\n");
}

// ===================== K1: single QK pass -> e=exp(z)*mask to gmem + inv =====================
// 512 threads, warp grid 4(q) x 4(s), warp tile 32q x 32s. Q-frags in registers.
extern "C" __global__ void __launch_bounds__(512, 1)
mha_qk_kernel(const float* __restrict__ Qg, const float* __restrict__ Kg,
              const int* __restrict__ Mg, float* __restrict__ Ag) {
    extern __shared__ float smf[];
    float* Ks = smf;                 // 2 x 128 x KS_S (raw f32, cvt at frag load)
    float* Ms = Ks + 2 * STT * KS_S; // mask row, SL floats
    float* Rs = Ms + SL;             // 4 x 128 partial rowsums (per wn)

    const int tid = threadIdx.x;
    const int lane = tid & 31, wid = tid >> 5;
    const int g = lane >> 2, lt = lane & 3;
    const int wm = wid >> 2, wn = wid & 3;
    const int b = blockIdx.z, h = blockIdx.y, q0 = blockIdx.x * QT;

    const float* gkb = Kg + ((size_t)b * SL) * DM + h * DH;
    const uint32_t ks_base = (uint32_t)__cvta_generic_to_shared(Ks);

    // mask row
    for (int j = tid; j < SL; j += 512) Ms[j] = (float)Mg[b * SL + j];

    // Q fragments -> registers (scale 1/8, tf32 RNA); rows wm*32 .. wm*32+31
    uint32_t qfr[2][8][4];
    {
        const float* gq = Qg + ((size_t)(b * QL + q0)) * DM + h * DH;
        #pragma unroll
        for (int mi = 0; mi < 2; mi++) {
            int r = wm * 32 + mi * 16 + g;
            #pragma unroll
            for (int kk = 0; kk < 8; kk++) {
                qfr[mi][kk][0] = tf32b(__ldg(gq + (size_t)r * DM + kk * 8 + lt) * 0.125f);
                qfr[mi][kk][1] = tf32b(__ldg(gq + (size_t)(r + 8) * DM + kk * 8 + lt) * 0.125f);
                qfr[mi][kk][2] = tf32b(__ldg(gq + (size_t)r * DM + kk * 8 + lt + 4) * 0.125f);
                qfr[mi][kk][3] = tf32b(__ldg(gq + (size_t)(r + 8) * DM + kk * 8 + lt + 4) * 0.125f);
            }
        }
    }

    // staging coords: 512 threads x 4 float4 = 128 rows x 64 cols
    int srow[4], scol[4];
    #pragma unroll
    for (int j = 0; j < 4; j++) {
        int idx = tid + j * 512;
        srow[j] = idx >> 4;
        scol[j] = (idx & 15) << 2;
    }
    auto stage = [&](int sc, int bi) {
        const float* gk = gkb + (size_t)sc * STT * DM;
        const uint32_t kd = ks_base + (uint32_t)(bi * STT * KS_S) * 4;
        #pragma unroll
        for (int j = 0; j < 4; j++)
            cp_async16(kd + (uint32_t)(srow[j] * KS_S + scol[j]) * 4,
                       gk + (size_t)srow[j] * DM + scol[j]);
        cp_commit();
    };

    float rs_acc[2][2] = {{0.f, 0.f}, {0.f, 0.f}};
    stage(0, 0);

    for (int sc = 0; sc < NCH; sc++) {
        if (sc + 1 < NCH) stage(sc + 1, (sc + 1) & 1);
        else cp_commit();
        cp_wait1();
        __syncthreads();
        const float* Kc = Ks + (sc & 1) * STT * KS_S;

        float acc[2][4][4];
        #pragma unroll
        for (int mi = 0; mi < 2; mi++)
            #pragma unroll
            for (int ni = 0; ni < 4; ni++)
                #pragma unroll
                for (int j = 0; j < 4; j++) acc[mi][ni][j] = 0.f;

        #pragma unroll
        for (int kk = 0; kk < 8; kk++) {
            #pragma unroll
            for (int ni = 0; ni < 4; ni++) {
                int c = wn * 32 + ni * 8 + g;
                uint32_t bfr[2];
                bfr[0] = tf32b(Kc[c * KS_S + kk * 8 + lt]);
                bfr[1] = tf32b(Kc[c * KS_S + kk * 8 + lt + 4]);
                mma8(acc[0][ni], qfr[0][kk], bfr);
                mma8(acc[1][ni], qfr[1][kk], bfr);
            }
        }

        // epilogue: e = exp(z)*mask -> gmem (32B sector quads), rowsum partials in regs
        const int s0 = sc * STT;
        #pragma unroll
        for (int mi = 0; mi < 2; mi++)
            #pragma unroll
            for (int half = 0; half < 2; half++) {
                int r = wm * 32 + mi * 16 + g + half * 8;
                float* ga = Ag + ((size_t)((b * QL + q0 + r) * H_ + h)) * SL
                               + s0 + wn * 32;
                float rloc = 0.f;
                #pragma unroll
                for (int ni = 0; ni < 4; ni++) {
                    int mc = s0 + wn * 32 + ni * 8 + 2 * lt;
                    float2 ev;
                    ev.x = __expf(acc[mi][ni][half * 2 + 0]) * Ms[mc];
                    ev.y = __expf(acc[mi][ni][half * 2 + 1]) * Ms[mc + 1];
                    rloc += ev.x + ev.y;
                    __stcs((float2*)(ga + ni * 8 + 2 * lt), ev);
                }
                rs_acc[mi][half] += rloc;
            }
        __syncthreads();   // buffer (sc&1) free before it is restaged at sc+2
    }

    // reduce rowsums: over lt within quad, then over wn via smem
    #pragma unroll
    for (int mi = 0; mi < 2; mi++)
        #pragma unroll
        for (int half = 0; half < 2; half++) {
            float v = rs_acc[mi][half];
            v += __shfl_xor_sync(0xffffffffu, v, 1);
            v += __shfl_xor_sync(0xffffffffu, v, 2);
            if (lt == 0) {
                int r = wm * 32 + mi * 16 + g + half * 8;
                Rs[wn * 128 + r] = v;
            }
        }
    __syncthreads();
    if (tid < QT) {
        float s = Rs[tid] + Rs[128 + tid] + Rs[256 + tid] + Rs[384 + tid];
        InvG[((size_t)(b * H_ + h)) * QL + q0 + tid] = 1.0f / (s + 1e-13f);
    }
}

// ===================== K2: normalize attn + O = (e @ V) * inv =====================
extern "C" __global__ void __launch_bounds__(256, 2)
mha_pv_kernel(float* __restrict__ Ag, const float* __restrict__ Vg,
              float* __restrict__ Og) {
    extern __shared__ float smf[];
    float* As = smf;                   // 2 x 128 x AS_S (raw e)
    float* Vs = As + 2 * QT * AS_S;    // 2 x 64 x VS_S
    float* Iv = Vs + 2 * KC * VS_S;    // 128 inv values

    const int tid = threadIdx.x;
    const int lane = tid & 31, wid = tid >> 5;
    const int g = lane >> 2, lt = lane & 3;
    const int wm = wid >> 1, wn = wid & 1;   // 4(q) x 2(dv), warp tile 32x32
    const int b = blockIdx.z, h = blockIdx.y, q0 = blockIdx.x * QT;

    const uint32_t as_base = (uint32_t)__cvta_generic_to_shared(As);
    const uint32_t vs_base = (uint32_t)__cvta_generic_to_shared(Vs);

    if (tid < QT) Iv[tid] = InvG[((size_t)(b * H_ + h)) * QL + q0 + tid];

    int ar[8], ac[8];
    #pragma unroll
    for (int j = 0; j < 8; j++) {
        int idx = tid + j * 256;           // 128 x 64 floats / 4
        ar[j] = idx >> 4;
        ac[j] = (idx & 15) << 2;
    }
    int vr[4], vc[4];
    #pragma unroll
    for (int j = 0; j < 4; j++) {
        int idx = tid + j * 256;           // 64 x 64 floats / 4
        vr[j] = idx >> 4;
        vc[j] = (idx & 15) << 2;
    }

    float* gab = Ag + ((size_t)((b * QL + q0) * H_ + h)) * SL;  // row stride H_*SL
    const float* gvb = Vg + ((size_t)b * SL) * DM + h * DH;

    auto stage = [&](int kc, int bi) {
        const int s0 = kc * KC;
        const uint32_t ad = as_base + (uint32_t)(bi * QT * AS_S) * 4;
        #pragma unroll
        for (int j = 0; j < 8; j++)
            cp_async16(ad + (uint32_t)(ar[j] * AS_S + ac[j]) * 4,
                       gab + (size_t)ar[j] * (H_ * SL) + s0 + ac[j]);
        const uint32_t vd = vs_base + (uint32_t)(bi * KC * VS_S) * 4;
        #pragma unroll
        for (int j = 0; j < 4; j++)
            cp_async16(vd + (uint32_t)(vr[j] * VS_S + vc[j]) * 4,
                       gvb + (size_t)(kc * KC + vr[j]) * DM + vc[j]);
        cp_commit();
    };

    float oacc[2][4][4];
    #pragma unroll
    for (int mi = 0; mi < 2; mi++)
        #pragma unroll
        for (int ni = 0; ni < 4; ni++)
            #pragma unroll
            for (int j = 0; j < 4; j++) oacc[mi][ni][j] = 0.f;

    stage(0, 0);

    for (int kc = 0; kc < NKC; kc++) {
        if (kc + 1 < NKC) stage(kc + 1, (kc + 1) & 1);
        else cp_commit();
        cp_wait1();
        __syncthreads();

        const float* Ac = As + (kc & 1) * QT * AS_S;
        const float* Vc = Vs + (kc & 1) * KC * VS_S;

        // PV mma on raw e (RNA-rounded in registers)
        #pragma unroll
        for (int kk = 0; kk < 8; kk++) {
            uint32_t afr[2][4];
            #pragma unroll
            for (int mi = 0; mi < 2; mi++) {
                int r = wm * 32 + mi * 16 + g;
                afr[mi][0] = tf32b(Ac[r * AS_S + kk * 8 + lt]);
                afr[mi][1] = tf32b(Ac[(r + 8) * AS_S + kk * 8 + lt]);
                afr[mi][2] = tf32b(Ac[r * AS_S + kk * 8 + lt + 4]);
                afr[mi][3] = tf32b(Ac[(r + 8) * AS_S + kk * 8 + lt + 4]);
            }
            #pragma unroll
            for (int ni = 0; ni < 4; ni++) {
                int c = wn * 32 + ni * 8 + g;
                uint32_t bfr[2];
                bfr[0] = tf32b(Vc[(kk * 8 + lt) * VS_S + c]);
                bfr[1] = tf32b(Vc[(kk * 8 + lt + 4) * VS_S + c]);
                mma8(oacc[0][ni], afr[0], bfr);
                mma8(oacc[1][ni], afr[1], bfr);
            }
        }

        // normalized attention write-back: attn = e * inv[row]
        const int s0 = kc * KC;
        #pragma unroll
        for (int j = 0; j < 8; j++) {
            float4 v = *(const float4*)(Ac + ar[j] * AS_S + ac[j]);
            float iv = Iv[ar[j]];
            v.x *= iv; v.y *= iv; v.z *= iv; v.w *= iv;
            __stcs((float4*)(gab + (size_t)ar[j] * (H_ * SL) + s0 + ac[j]), v);
        }
        __syncthreads();   // buffer free before restage
    }

    // ---- write O tile, scaled by inv per row ----
    #pragma unroll
    for (int mi = 0; mi < 2; mi++) {
        int r = wm * 32 + mi * 16 + g;
        float iv0 = Iv[r], iv1 = Iv[r + 8];
        float* go = Og + ((size_t)(b * QL + q0 + r)) * DM + h * DH + wn * 32;
        #pragma unroll
        for (int ni = 0; ni < 4; ni++) {
            int c = ni * 8 + 2 * lt;
            float2 v0; v0.x = oacc[mi][ni][0] * iv0; v0.y = oacc[mi][ni][1] * iv0;
            float2 v1; v1.x = oacc[mi][ni][2] * iv1; v1.y = oacc[mi][ni][3] * iv1;
            __stcs((float2*)(go + c), v0);
            __stcs((float2*)(go + (size_t)8 * DM + c), v1);
        }
    }
}

extern "C" void kernel_launch(void* const* d_in, const int* in_sizes, int n_in,
                              void* d_out, int out_size) {
    const float* Qg = (const float*)d_in[0];
    const float* Kg = (const float*)d_in[1];
    const float* Vg = (const float*)d_in[2];
    const int*   Mg = (const int*)d_in[3];

    float* Og = (float*)d_out;
    float* Ag = Og + (size_t)B_ * QL * DM;   // attention region of d_out

    cudaFuncSetAttribute(mha_qk_kernel,
                         cudaFuncAttributeMaxDynamicSharedMemorySize,
                         K1_SMEM_FLOATS * (int)sizeof(float));
    cudaFuncSetAttribute(mha_pv_kernel,
                         cudaFuncAttributeMaxDynamicSharedMemorySize,
                         K2_SMEM_FLOATS * (int)sizeof(float));

    dim3 grid(QL / QT, H_, B_);
    mha_qk_kernel<<<grid, 512, K1_SMEM_FLOATS * sizeof(float)>>>(Qg, Kg, Mg, Ag);
    mha_pv_kernel<<<grid, 256, K2_SMEM_FLOATS * sizeof(float)>>>(Ag, Vg, Og);
}